// round 12
// baseline (speedup 1.0000x reference)
#include <cuda_runtime.h>
#include <cuda_bf16.h>
#include <cstdint>
#include <cstddef>

#define NN 100000
#define EE 800000
#define DD 128
#define NCLS 64

// ---------------------------------------------------------------------------
// Scratch (no runtime allocation allowed)
// ---------------------------------------------------------------------------
__device__ float g_m   [(size_t)NN * DD];
__device__ float g_agg [(size_t)NN * DD];
__device__ float g_self[(size_t)NN * DD];
__device__ float g_h1  [(size_t)NN * DD];
__device__ float g_h2  [(size_t)NN * DD];
__device__ __nv_bfloat16 g_wh[9][DD * DD];
__device__ __nv_bfloat16 g_wl[9][DD * DD];
__device__ int g_deg[NN];
__device__ int g_off[NN];
__device__ int g_cur[NN];
__device__ int g_csr[EE];
__device__ int g_part[128];

// ---------------------------------------------------------------------------
// Weight prep
// ---------------------------------------------------------------------------
struct WPrep { const float* src[9]; int M[9]; };

__global__ void prep_weights(WPrep p, __nv_bfloat16* __restrict__ hi,
                             __nv_bfloat16* __restrict__ lo)
{
    int w = blockIdx.y;
    int M = p.M[w];
    int idx = blockIdx.x * blockDim.x + threadIdx.x;
    if (idx >= DD * M) return;
    int k = idx / M;
    int m = idx % M;
    float v = p.src[w][idx];
    __nv_bfloat16 h = __float2bfloat16(v);
    float r = v - __bfloat162float(h);
    hi[(size_t)w * DD * DD + m * DD + k] = h;
    lo[(size_t)w * DD * DD + m * DD + k] = __float2bfloat16(r);
}

// ---------------------------------------------------------------------------
// CSR build
// ---------------------------------------------------------------------------
__global__ void zero_deg_kernel()
{
    int i = blockIdx.x * blockDim.x + threadIdx.x;
    if (i < NN) g_deg[i] = 0;
}

__global__ void count_kernel(const int* __restrict__ dst)
{
    int e = blockIdx.x * blockDim.x + threadIdx.x;
    if (e < EE) atomicAdd(&g_deg[dst[e]], 1);
}

__global__ void scan1_kernel()
{
    __shared__ int sh[256];
    int tid = threadIdx.x;
    int base = blockIdx.x * 1024 + tid * 4;
    int s = 0;
    #pragma unroll
    for (int j = 0; j < 4; j++) {
        int idx = base + j;
        if (idx < NN) s += g_deg[idx];
    }
    sh[tid] = s;
    __syncthreads();
    for (int o = 128; o; o >>= 1) {
        if (tid < o) sh[tid] += sh[tid + o];
        __syncthreads();
    }
    if (tid == 0) g_part[blockIdx.x] = sh[0];
}

__global__ void scan3_kernel(int nblk)
{
    __shared__ int sh[256];
    int tid = threadIdx.x;
    int base = blockIdx.x * 1024 + tid * 4;
    int v[4];
    int s = 0;
    #pragma unroll
    for (int j = 0; j < 4; j++) {
        int idx = base + j;
        v[j] = (idx < NN) ? g_deg[idx] : 0;
        s += v[j];
    }
    sh[tid] = s;
    __syncthreads();
    #pragma unroll
    for (int o = 1; o < 256; o <<= 1) {
        int x = (tid >= o) ? sh[tid - o] : 0;
        __syncthreads();
        sh[tid] += x;
        __syncthreads();
    }
    int pre = 0;
    for (int i = 0; i < blockIdx.x; i++) pre += __ldg(&g_part[i]);
    int run = sh[tid] - s + pre;
    #pragma unroll
    for (int j = 0; j < 4; j++) {
        int idx = base + j;
        if (idx < NN) { g_off[idx] = run; g_cur[idx] = run; }
        run += v[j];
    }
}

__global__ void fill_kernel(const int* __restrict__ src,
                            const int* __restrict__ dst)
{
    int e = blockIdx.x * blockDim.x + threadIdx.x;
    if (e < EE) {
        int p = atomicAdd(&g_cur[dst[e]], 1);
        g_csr[p] = src[e];
    }
}

// ---------------------------------------------------------------------------
// mma / ldmatrix / cp.async helpers
// ---------------------------------------------------------------------------
__device__ __forceinline__ void mma16(float* c, const uint32_t* a,
                                      uint32_t b0, uint32_t b1)
{
    asm("mma.sync.aligned.m16n8k16.row.col.f32.bf16.bf16.f32 "
        "{%0,%1,%2,%3}, {%4,%5,%6,%7}, {%8,%9}, {%0,%1,%2,%3};\n"
        : "+f"(c[0]), "+f"(c[1]), "+f"(c[2]), "+f"(c[3])
        : "r"(a[0]), "r"(a[1]), "r"(a[2]), "r"(a[3]),
          "r"(b0), "r"(b1));
}

__device__ __forceinline__ void ldmx4(uint32_t* r, uint32_t addr)
{
    asm volatile(
        "ldmatrix.sync.aligned.m8n8.x4.shared.b16 {%0,%1,%2,%3}, [%4];"
        : "=r"(r[0]), "=r"(r[1]), "=r"(r[2]), "=r"(r[3]) : "r"(addr));
}

__device__ __forceinline__ void cp16(uint32_t saddr, const void* gaddr)
{
    asm volatile("cp.async.cg.shared.global [%0], [%1], 16;\n"
                 :: "r"(saddr), "l"(gaddr));
}
__device__ __forceinline__ void cp_commit()
{ asm volatile("cp.async.commit_group;\n"); }
__device__ __forceinline__ void cp_wait0()
{ asm volatile("cp.async.wait_group 0;\n"); }

__device__ __forceinline__ uint32_t pack_bf16x2(float a, float b)
{
    __nv_bfloat162 h = __floats2bfloat162_rn(a, b);
    return *reinterpret_cast<uint32_t*>(&h);
}

// ---------------------------------------------------------------------------
// Aggregation block body: warp per node, gather-max, MLP-8 unroll.
// (runs as agg-typed blocks inside the combined kernel)
// ---------------------------------------------------------------------------
__device__ __forceinline__ void agg_body(const float* __restrict__ m,
                                         float* __restrict__ agg,
                                         int aggid, int N)
{
    int node = aggid * 8 + (threadIdx.x >> 5);
    int lane = threadIdx.x & 31;
    if (node >= N) return;
    int o = g_off[node];
    int d = g_deg[node];
    float4 acc = make_float4(0.f, 0.f, 0.f, 0.f);
    int i = 0;
    for (; i + 8 <= d; i += 8) {
        int s[8];
        #pragma unroll
        for (int j = 0; j < 8; j++) s[j] = g_csr[o + i + j];
        float4 v[8];
        #pragma unroll
        for (int j = 0; j < 8; j++)
            v[j] = *reinterpret_cast<const float4*>(&m[(size_t)s[j] * DD + lane * 4]);
        #pragma unroll
        for (int j = 0; j < 8; j++) {
            acc.x = fmaxf(acc.x, v[j].x);
            acc.y = fmaxf(acc.y, v[j].y);
            acc.z = fmaxf(acc.z, v[j].z);
            acc.w = fmaxf(acc.w, v[j].w);
        }
    }
    for (; i + 4 <= d; i += 4) {
        int s[4];
        #pragma unroll
        for (int j = 0; j < 4; j++) s[j] = g_csr[o + i + j];
        float4 v[4];
        #pragma unroll
        for (int j = 0; j < 4; j++)
            v[j] = *reinterpret_cast<const float4*>(&m[(size_t)s[j] * DD + lane * 4]);
        #pragma unroll
        for (int j = 0; j < 4; j++) {
            acc.x = fmaxf(acc.x, v[j].x);
            acc.y = fmaxf(acc.y, v[j].y);
            acc.z = fmaxf(acc.z, v[j].z);
            acc.w = fmaxf(acc.w, v[j].w);
        }
    }
    for (; i < d; i++) {
        int s = g_csr[o + i];
        float4 v = *reinterpret_cast<const float4*>(&m[(size_t)s * DD + lane * 4]);
        acc.x = fmaxf(acc.x, v.x);
        acc.y = fmaxf(acc.y, v.y);
        acc.z = fmaxf(acc.z, v.z);
        acc.w = fmaxf(acc.w, v.w);
    }
    *reinterpret_cast<float4*>(&agg[(size_t)node * DD + lane * 4]) = acc;
}

// ---------------------------------------------------------------------------
// GEMM tile body: C-tile[128 x 64] = A @ W (bf16 hi/lo split, 3 products),
// K = 128 (2 k-tiles of 64), B double-buffered cp.async, A register-staged,
// single 8-wide ldmatrix burst per k-step, 24 MMAs product-major.
// MODE 0: relu(c + bias) -> C           (pool)
// MODE 1: raw c -> C                    (self)
// MODE 2: relu(c + bias + S) -> C       (neigh)
// MODE 3: relu(c + bias + S), row log-softmax -> C   (final neigh, M=64)
// ---------------------------------------------------------------------------
template<int MODE>
__device__ __forceinline__ void gemm_tile_body(
    const float* __restrict__ A,
    const __nv_bfloat16* __restrict__ Bh,
    const __nv_bfloat16* __restrict__ Bl,
    const float* __restrict__ bias,
    const float* __restrict__ Sin,
    float* __restrict__ C,
    int N, int M, int tcol, int trow)
{
    constexpr int BM   = 128;
    constexpr int BN   = 64;
    constexpr int BK   = 64;
    constexpr int STRP = 36;
    constexpr int NT   = 4;
    constexpr int NP   = 2;
    constexpr int BBUF = BN * STRP;

    extern __shared__ __align__(16) uint32_t smem_u[];
    uint32_t* As_hi = smem_u;
    uint32_t* As_lo = As_hi + BM * STRP;
    uint32_t* Bs    = As_lo + BM * STRP;

    const int tid  = threadIdx.x;
    const int lane = tid & 31;
    const int warp = tid >> 5;
    const int wm   = warp & 3;
    const int wn   = warp >> 2;
    const int t4   = lane & 3;
    const int brow = trow * BM;
    const int coff = tcol * BN;

    Bh += (size_t)coff * DD;
    Bl += (size_t)coff * DD;
    if (MODE != 1) bias += coff;

    const uint32_t as_hi_b = (uint32_t)__cvta_generic_to_shared(As_hi);
    const uint32_t as_lo_b = (uint32_t)__cvta_generic_to_shared(As_lo);
    const uint32_t bs_b    = (uint32_t)__cvta_generic_to_shared(Bs);

    const uint32_t a_row_off = (uint32_t)(lane & 15) * STRP + (uint32_t)(lane >> 4) * 4;
    const uint32_t b_row_off = ((uint32_t)(lane & 7) + (uint32_t)(lane >> 4) * 8) * STRP
                             + (uint32_t)((lane >> 3) & 1) * 4;

    float c[2][NT][4];
    #pragma unroll
    for (int mt = 0; mt < 2; mt++)
        #pragma unroll
        for (int nt = 0; nt < NT; nt++)
            #pragma unroll
            for (int i = 0; i < 4; i++) c[mt][nt][i] = 0.0f;

    float4 areg[8];

    #define LOAD_A_REG(t_) do {                                               \
        int koff_ = (t_) * BK;                                                \
        _Pragma("unroll")                                                     \
        for (int l = 0; l < 8; l++) {                                         \
            int idx = tid + l * 256;                                          \
            int r   = idx >> 4;                                               \
            int c4  = idx & 15;                                               \
            int grow = brow + r;                                              \
            areg[l] = (grow < N)                                              \
                ? *reinterpret_cast<const float4*>(                           \
                      &A[(size_t)grow * DD + koff_ + c4 * 4])                 \
                : make_float4(0.f, 0.f, 0.f, 0.f);                            \
        }                                                                     \
    } while (0)

    #define STORE_A_SMEM() do {                                               \
        _Pragma("unroll")                                                     \
        for (int l = 0; l < 8; l++) {                                         \
            int idx = tid + l * 256;                                          \
            int r   = idx >> 4;                                               \
            int c4  = idx & 15;                                               \
            float4 v = areg[l];                                               \
            float hx = __bfloat162float(__float2bfloat16(v.x));               \
            float hy = __bfloat162float(__float2bfloat16(v.y));               \
            float hz = __bfloat162float(__float2bfloat16(v.z));               \
            float hw = __bfloat162float(__float2bfloat16(v.w));               \
            uint32_t* ph = &As_hi[r * STRP + c4 * 2];                         \
            uint32_t* pl = &As_lo[r * STRP + c4 * 2];                         \
            ph[0] = pack_bf16x2(hx, hy);                                      \
            ph[1] = pack_bf16x2(hz, hw);                                      \
            pl[0] = pack_bf16x2(v.x - hx, v.y - hy);                          \
            pl[1] = pack_bf16x2(v.z - hz, v.w - hw);                          \
        }                                                                     \
    } while (0)

    #define CPASYNC_B(t_, buf_) do {                                          \
        const __nv_bfloat16* Bh_ = Bh + (t_) * BK;                            \
        const __nv_bfloat16* Bl_ = Bl + (t_) * BK;                            \
        uint32_t hi_base = bs_b + (uint32_t)(buf_) * 2u * BBUF * 4u;          \
        uint32_t lo_base = hi_base + (uint32_t)BBUF * 4u;                     \
        _Pragma("unroll")                                                     \
        for (int l = 0; l < 2; l++) {                                         \
            int idx = tid + l * 256;                                          \
            int n   = idx >> 3;                                               \
            int q   = idx & 7;                                                \
            uint32_t so = (uint32_t)(n * STRP + q * 4) * 4u;                  \
            cp16(hi_base + so, &Bh_[(size_t)n * DD + q * 8]);                 \
            cp16(lo_base + so, &Bl_[(size_t)n * DD + q * 8]);                 \
        }                                                                     \
        cp_commit();                                                          \
    } while (0)

    // ---- prologue ----
    LOAD_A_REG(0);
    CPASYNC_B(0, 0);
    STORE_A_SMEM();
    cp_wait0();
    __syncthreads();

    // ---- 2 pipelined k-tiles ----
    #pragma unroll 1
    for (int t = 0; t < 2; t++) {
        int buf = t & 1;
        bool has_next = (t == 0);
        if (has_next) {
            LOAD_A_REG(1);
            CPASYNC_B(1, 1);
        }

        uint32_t bhi_base = bs_b + (uint32_t)buf * 2u * BBUF * 4u;
        uint32_t blo_base = bhi_base + (uint32_t)BBUF * 4u;

        #pragma unroll
        for (int ks = 0; ks < BK / 16; ks++) {
            int kp = ks * 8;
            uint32_t ah[2][4], al[2][4], bh[NP][4], bl[NP][4];
            #pragma unroll
            for (int mt = 0; mt < 2; mt++) {
                uint32_t off = ((uint32_t)(wm * 32 + mt * 16) * STRP
                                + (uint32_t)kp + a_row_off) * 4u;
                ldmx4(ah[mt], as_hi_b + off);
                ldmx4(al[mt], as_lo_b + off);
            }
            #pragma unroll
            for (int p = 0; p < NP; p++) {
                uint32_t off = ((uint32_t)(wn * 32 + p * 16) * STRP
                                + (uint32_t)kp + b_row_off) * 4u;
                ldmx4(bh[p], bhi_base + off);
                ldmx4(bl[p], blo_base + off);
            }
            #pragma unroll
            for (int p = 0; p < NP; p++)
                #pragma unroll
                for (int sub = 0; sub < 2; sub++)
                    #pragma unroll
                    for (int mt = 0; mt < 2; mt++)
                        mma16(c[mt][p*2+sub], ah[mt], bh[p][2*sub], bh[p][2*sub+1]);
            #pragma unroll
            for (int p = 0; p < NP; p++)
                #pragma unroll
                for (int sub = 0; sub < 2; sub++)
                    #pragma unroll
                    for (int mt = 0; mt < 2; mt++)
                        mma16(c[mt][p*2+sub], ah[mt], bl[p][2*sub], bl[p][2*sub+1]);
            #pragma unroll
            for (int p = 0; p < NP; p++)
                #pragma unroll
                for (int sub = 0; sub < 2; sub++)
                    #pragma unroll
                    for (int mt = 0; mt < 2; mt++)
                        mma16(c[mt][p*2+sub], al[mt], bh[p][2*sub], bh[p][2*sub+1]);
        }
        __syncthreads();
        if (has_next) {
            STORE_A_SMEM();
            cp_wait0();
            __syncthreads();
        }
    }

    const int g = lane >> 2;

    if (MODE == 0 || MODE == 1 || MODE == 2) {
        #pragma unroll
        for (int mt = 0; mt < 2; mt++) {
            int row = brow + wm * 32 + mt * 16 + g;
            #pragma unroll
            for (int nt = 0; nt < NT; nt++) {
                int col = wn * 32 + nt * 8 + 2 * t4;
                int gcol = coff + col;
                float b0 = 0.f, b1 = 0.f;
                if (MODE != 1) { b0 = bias[col]; b1 = bias[col + 1]; }
                if (row < N) {
                    float2 v;
                    if (MODE == 1) {
                        v.x = c[mt][nt][0];
                        v.y = c[mt][nt][1];
                    } else if (MODE == 0) {
                        v.x = fmaxf(c[mt][nt][0] + b0, 0.0f);
                        v.y = fmaxf(c[mt][nt][1] + b1, 0.0f);
                    } else {
                        float2 s = *reinterpret_cast<const float2*>(
                                       &Sin[(size_t)row * M + gcol]);
                        v.x = fmaxf(c[mt][nt][0] + b0 + s.x, 0.0f);
                        v.y = fmaxf(c[mt][nt][1] + b1 + s.y, 0.0f);
                    }
                    *reinterpret_cast<float2*>(&C[(size_t)row * M + gcol]) = v;
                }
                if (row + 8 < N) {
                    float2 v;
                    if (MODE == 1) {
                        v.x = c[mt][nt][2];
                        v.y = c[mt][nt][3];
                    } else if (MODE == 0) {
                        v.x = fmaxf(c[mt][nt][2] + b0, 0.0f);
                        v.y = fmaxf(c[mt][nt][3] + b1, 0.0f);
                    } else {
                        float2 s = *reinterpret_cast<const float2*>(
                                       &Sin[(size_t)(row + 8) * M + gcol]);
                        v.x = fmaxf(c[mt][nt][2] + b0 + s.x, 0.0f);
                        v.y = fmaxf(c[mt][nt][3] + b1 + s.y, 0.0f);
                    }
                    *reinterpret_cast<float2*>(&C[(size_t)(row + 8) * M + gcol]) = v;
                }
            }
        }
    } else {
        // MODE 3: relu(c + bias + S) -> smem, row log-softmax (M=64) -> C
        constexpr int SSTR = 68;
        float* sf = reinterpret_cast<float*>(smem_u);
        #pragma unroll
        for (int mt = 0; mt < 2; mt++) {
            int rl = wm * 32 + mt * 16 + g;
            int row = brow + rl;
            #pragma unroll
            for (int nt = 0; nt < NT; nt++) {
                int col = wn * 32 + nt * 8 + 2 * t4;
                float b0 = bias[col], b1 = bias[col + 1];
                float2 s0 = make_float2(0.f, 0.f), s1 = make_float2(0.f, 0.f);
                if (row < N)
                    s0 = *reinterpret_cast<const float2*>(&Sin[(size_t)row * M + col]);
                if (row + 8 < N)
                    s1 = *reinterpret_cast<const float2*>(&Sin[(size_t)(row + 8) * M + col]);
                float2 v0, v1;
                v0.x = fmaxf(c[mt][nt][0] + b0 + s0.x, 0.0f);
                v0.y = fmaxf(c[mt][nt][1] + b1 + s0.y, 0.0f);
                v1.x = fmaxf(c[mt][nt][2] + b0 + s1.x, 0.0f);
                v1.y = fmaxf(c[mt][nt][3] + b1 + s1.y, 0.0f);
                *reinterpret_cast<float2*>(&sf[rl * SSTR + col])       = v0;
                *reinterpret_cast<float2*>(&sf[(rl + 8) * SSTR + col]) = v1;
            }
        }
        __syncthreads();
        #pragma unroll 1
        for (int r = warp; r < BM; r += 8) {
            int grow = brow + r;
            if (grow >= N) continue;
            float v0 = sf[r * SSTR + lane];
            float v1 = sf[r * SSTR + lane + 32];
            float mx = fmaxf(v0, v1);
            #pragma unroll
            for (int o = 16; o; o >>= 1)
                mx = fmaxf(mx, __shfl_xor_sync(0xFFFFFFFFu, mx, o));
            float s = expf(v0 - mx) + expf(v1 - mx);
            #pragma unroll
            for (int o = 16; o; o >>= 1)
                s += __shfl_xor_sync(0xFFFFFFFFu, s, o);
            float lse = logf(s) + mx;
            C[(size_t)grow * NCLS + lane]      = v0 - lse;
            C[(size_t)grow * NCLS + lane + 32] = v1 - lse;
        }
    }
    #undef LOAD_A_REG
    #undef STORE_A_SMEM
    #undef CPASYNC_B
}

// ---------------------------------------------------------------------------
// Plain GEMM kernel (pool / neigh / final)
// ---------------------------------------------------------------------------
template<int MODE>
__global__ void __launch_bounds__(256, 2)
gemm_kernel(const float* __restrict__ A,
            const __nv_bfloat16* __restrict__ Bh,
            const __nv_bfloat16* __restrict__ Bl,
            const float* __restrict__ bias,
            const float* __restrict__ Sin,
            float* __restrict__ C, int N, int M)
{
    gemm_tile_body<MODE>(A, Bh, Bl, bias, Sin, C, N, M,
                         blockIdx.x, blockIdx.y);
}

// ---------------------------------------------------------------------------
// Combined kernel: self-GEMM tiles (every RST-th block) + aggregation blocks.
// Both inputs (h for self, m for agg) ready at launch -> overlap tensor and
// memory pipes on co-resident CTAs.
// ---------------------------------------------------------------------------
__global__ void __launch_bounds__(256, 2)
self_agg_kernel(const float* __restrict__ A,
                const __nv_bfloat16* __restrict__ Bh,
                const __nv_bfloat16* __restrict__ Bl,
                float* __restrict__ Sout, int Mself, int CT,
                const float* __restrict__ m,
                float* __restrict__ agg, int N, int RST)
{
    int b = blockIdx.x;
    if (b % RST == 0) {
        int t = b / RST;
        gemm_tile_body<1>(A, Bh, Bl, nullptr, nullptr, Sout, N, Mself,
                          t % CT, t / CT);
    } else {
        int aggid = b - b / RST - 1;
        agg_body(m, agg, aggid, N);
    }
}

// ---------------------------------------------------------------------------
// Launch
// ---------------------------------------------------------------------------
extern "C" void kernel_launch(void* const* d_in, const int* in_sizes, int n_in,
                              void* d_out, int out_size)
{
    const float* x    = (const float*)d_in[0];
    const int*   esrc = (const int*)  d_in[1];
    const int*   edst = (const int*)  d_in[2];

    const float* Wp[3], *bp[3], *Ws[3], *Wn[3], *bn[3];
    for (int i = 0; i < 3; i++) {
        Wp[i] = (const float*)d_in[3 + 5 * i + 0];
        bp[i] = (const float*)d_in[3 + 5 * i + 1];
        Ws[i] = (const float*)d_in[3 + 5 * i + 2];
        Wn[i] = (const float*)d_in[3 + 5 * i + 3];
        bn[i] = (const float*)d_in[3 + 5 * i + 4];
    }

    float *m_p, *agg_p, *self_p, *h1_p, *h2_p;
    cudaGetSymbolAddress((void**)&m_p,    g_m);
    cudaGetSymbolAddress((void**)&agg_p,  g_agg);
    cudaGetSymbolAddress((void**)&self_p, g_self);
    cudaGetSymbolAddress((void**)&h1_p,   g_h1);
    cudaGetSymbolAddress((void**)&h2_p,   g_h2);
    __nv_bfloat16 *wh_p, *wl_p;
    cudaGetSymbolAddress((void**)&wh_p, g_wh);
    cudaGetSymbolAddress((void**)&wl_p, g_wl);

    const int N = NN, E = EE;

    size_t smemG = (size_t)(2 * 128 * 36 + 4 * 64 * 36) * 4;  // 73728
    cudaFuncSetAttribute(gemm_kernel<0>,
                         cudaFuncAttributeMaxDynamicSharedMemorySize, (int)smemG);
    cudaFuncSetAttribute(gemm_kernel<2>,
                         cudaFuncAttributeMaxDynamicSharedMemorySize, (int)smemG);
    cudaFuncSetAttribute(gemm_kernel<3>,
                         cudaFuncAttributeMaxDynamicSharedMemorySize, (int)smemG);
    cudaFuncSetAttribute(self_agg_kernel,
                         cudaFuncAttributeMaxDynamicSharedMemorySize, (int)smemG);

    // launch 1: weight prep
    WPrep wp;
    const float* wsrc[9] = { Wp[0], Ws[0], Wn[0],
                             Wp[1], Ws[1], Wn[1],
                             Wp[2], Ws[2], Wn[2] };
    int wM[9] = { DD, DD, DD, DD, DD, DD, DD, NCLS, NCLS };
    for (int i = 0; i < 9; i++) { wp.src[i] = wsrc[i]; wp.M[i] = wM[i]; }
    prep_weights<<<dim3((DD * DD + 255) / 256, 9), 256>>>(wp, wh_p, wl_p);

    // launch 2-3: CSR part 1
    zero_deg_kernel<<<(NN + 255) / 256, 256>>>();
    count_kernel<<<(E + 255) / 256, 256>>>(edst);

    const int RT = (N + 127) / 128;           // 782 row tiles
    dim3 grid2(2, RT);
    dim3 grid1(1, RT);

    // launch 4: layer-0 pool GEMM (profiled slot)
    gemm_kernel<0><<<grid2, 256, smemG>>>(
        x, wh_p + 0 * DD * DD, wl_p + 0 * DD * DD,
        bp[0], nullptr, m_p, N, DD);

    // launches 5-7: CSR part 2 (independent of GEMM)
    const int SCAN_BLKS = (NN + 1023) / 1024;    // 98
    scan1_kernel<<<SCAN_BLKS, 256>>>();
    scan3_kernel<<<SCAN_BLKS, 256>>>(SCAN_BLKS);
    fill_kernel<<<(E + 255) / 256, 256>>>(esrc, edst);

    const float* h = x;
    float* hbuf[2] = { h1_p, h2_p };

    for (int layer = 0; layer < 3; layer++) {
        const __nv_bfloat16* wph = wh_p + (layer * 3 + 0) * DD * DD;
        const __nv_bfloat16* wpl = wl_p + (layer * 3 + 0) * DD * DD;
        const __nv_bfloat16* wsh = wh_p + (layer * 3 + 1) * DD * DD;
        const __nv_bfloat16* wsl = wl_p + (layer * 3 + 1) * DD * DD;
        const __nv_bfloat16* wnh = wh_p + (layer * 3 + 2) * DD * DD;
        const __nv_bfloat16* wnl = wl_p + (layer * 3 + 2) * DD * DD;

        // 1) m = relu(h @ Wp + bp)  (layer 0 issued above)
        if (layer > 0) {
            gemm_kernel<0><<<grid2, 256, smemG>>>(
                h, wph, wpl, bp[layer], nullptr, m_p, N, DD);
        }

        // 2) combined: S = h @ Ws (raw)  ||  agg = segment_max(m[src], dst)
        if (layer < 2) {
            int G = 2 * RT, RST = 9;              // agg blocks = 8G = 12512
            self_agg_kernel<<<G * RST, 256, smemG>>>(
                h, wsh, wsl, self_p, DD, 2, m_p, agg_p, N, RST);
        } else {
            int G = RT, RST = 18;                 // agg blocks = 17G = 13294
            self_agg_kernel<<<G * RST, 256, smemG>>>(
                h, wsh, wsl, self_p, NCLS, 1, m_p, agg_p, N, RST);
        }

        // 3) h' = relu(S + agg @ Wn + bn)   (final layer + log-softmax)
        if (layer < 2) {
            float* out = hbuf[layer & 1];
            gemm_kernel<2><<<grid2, 256, smemG>>>(
                agg_p, wnh, wnl, bn[layer], self_p, out, N, DD);
            h = out;
        } else {
            gemm_kernel<3><<<grid1, 256, smemG>>>(
                agg_p, wnh, wnl, bn[layer], self_p, (float*)d_out, N, NCLS);
        }
    }
}

// round 15
// speedup vs baseline: 1.4168x; 1.4168x over previous
#include <cuda_runtime.h>
#include <cuda_bf16.h>
#include <cstdint>
#include <cstddef>

#define NN 100000
#define EE 800000
#define DD 128
#define NCLS 64

// ---------------------------------------------------------------------------
// Scratch (no runtime allocation allowed)
// ---------------------------------------------------------------------------
__device__ float g_m  [(size_t)NN * DD];
__device__ float g_agg[(size_t)NN * DD];
__device__ float g_h1 [(size_t)NN * DD];
__device__ float g_h2 [(size_t)NN * DD];
__device__ __nv_bfloat16 g_wh[9][DD * DD];
__device__ __nv_bfloat16 g_wl[9][DD * DD];
__device__ int g_deg[NN];
__device__ int g_off[NN];
__device__ int g_cur[NN];
__device__ int g_csr[EE];
__device__ int g_part[128];

// ---------------------------------------------------------------------------
// Weight prep
// ---------------------------------------------------------------------------
struct WPrep { const float* src[9]; int M[9]; };

__global__ void prep_weights(WPrep p, __nv_bfloat16* __restrict__ hi,
                             __nv_bfloat16* __restrict__ lo)
{
    int w = blockIdx.y;
    int M = p.M[w];
    int idx = blockIdx.x * blockDim.x + threadIdx.x;
    if (idx >= DD * M) return;
    int k = idx / M;
    int m = idx % M;
    float v = p.src[w][idx];
    __nv_bfloat16 h = __float2bfloat16(v);
    float r = v - __bfloat162float(h);
    hi[(size_t)w * DD * DD + m * DD + k] = h;
    lo[(size_t)w * DD * DD + m * DD + k] = __float2bfloat16(r);
}

// ---------------------------------------------------------------------------
// CSR build
// ---------------------------------------------------------------------------
__global__ void zero_deg_kernel()
{
    int i = blockIdx.x * blockDim.x + threadIdx.x;
    if (i < NN) g_deg[i] = 0;
}

__global__ void count_kernel(const int* __restrict__ dst)
{
    int e = blockIdx.x * blockDim.x + threadIdx.x;
    if (e < EE) atomicAdd(&g_deg[dst[e]], 1);
}

__global__ void scan1_kernel()
{
    __shared__ int sh[256];
    int tid = threadIdx.x;
    int base = blockIdx.x * 1024 + tid * 4;
    int s = 0;
    #pragma unroll
    for (int j = 0; j < 4; j++) {
        int idx = base + j;
        if (idx < NN) s += g_deg[idx];
    }
    sh[tid] = s;
    __syncthreads();
    for (int o = 128; o; o >>= 1) {
        if (tid < o) sh[tid] += sh[tid + o];
        __syncthreads();
    }
    if (tid == 0) g_part[blockIdx.x] = sh[0];
}

__global__ void scan3_kernel(int nblk)
{
    __shared__ int sh[256];
    int tid = threadIdx.x;
    int base = blockIdx.x * 1024 + tid * 4;
    int v[4];
    int s = 0;
    #pragma unroll
    for (int j = 0; j < 4; j++) {
        int idx = base + j;
        v[j] = (idx < NN) ? g_deg[idx] : 0;
        s += v[j];
    }
    sh[tid] = s;
    __syncthreads();
    #pragma unroll
    for (int o = 1; o < 256; o <<= 1) {
        int x = (tid >= o) ? sh[tid - o] : 0;
        __syncthreads();
        sh[tid] += x;
        __syncthreads();
    }
    int pre = 0;
    for (int i = 0; i < blockIdx.x; i++) pre += __ldg(&g_part[i]);
    int run = sh[tid] - s + pre;
    #pragma unroll
    for (int j = 0; j < 4; j++) {
        int idx = base + j;
        if (idx < NN) { g_off[idx] = run; g_cur[idx] = run; }
        run += v[j];
    }
}

__global__ void fill_kernel(const int* __restrict__ src,
                            const int* __restrict__ dst)
{
    int e = blockIdx.x * blockDim.x + threadIdx.x;
    if (e < EE) {
        int p = atomicAdd(&g_cur[dst[e]], 1);
        g_csr[p] = src[e];
    }
}

// ---------------------------------------------------------------------------
// Aggregation: warp per node, gather-max (no atomics), unrolled x4
// ---------------------------------------------------------------------------
__global__ void aggregate_kernel(const float* __restrict__ m,
                                 float* __restrict__ agg, int N)
{
    int node = blockIdx.x * 8 + (threadIdx.x >> 5);
    int lane = threadIdx.x & 31;
    if (node >= N) return;
    int o = g_off[node];
    int d = g_deg[node];
    float4 acc = make_float4(0.f, 0.f, 0.f, 0.f);
    int i = 0;
    for (; i + 4 <= d; i += 4) {
        int s0 = g_csr[o + i + 0];
        int s1 = g_csr[o + i + 1];
        int s2 = g_csr[o + i + 2];
        int s3 = g_csr[o + i + 3];
        float4 v0 = *reinterpret_cast<const float4*>(&m[(size_t)s0 * DD + lane * 4]);
        float4 v1 = *reinterpret_cast<const float4*>(&m[(size_t)s1 * DD + lane * 4]);
        float4 v2 = *reinterpret_cast<const float4*>(&m[(size_t)s2 * DD + lane * 4]);
        float4 v3 = *reinterpret_cast<const float4*>(&m[(size_t)s3 * DD + lane * 4]);
        acc.x = fmaxf(fmaxf(acc.x, fmaxf(v0.x, v1.x)), fmaxf(v2.x, v3.x));
        acc.y = fmaxf(fmaxf(acc.y, fmaxf(v0.y, v1.y)), fmaxf(v2.y, v3.y));
        acc.z = fmaxf(fmaxf(acc.z, fmaxf(v0.z, v1.z)), fmaxf(v2.z, v3.z));
        acc.w = fmaxf(fmaxf(acc.w, fmaxf(v0.w, v1.w)), fmaxf(v2.w, v3.w));
    }
    for (; i < d; i++) {
        int s = g_csr[o + i];
        float4 v = *reinterpret_cast<const float4*>(&m[(size_t)s * DD + lane * 4]);
        acc.x = fmaxf(acc.x, v.x);
        acc.y = fmaxf(acc.y, v.y);
        acc.z = fmaxf(acc.z, v.z);
        acc.w = fmaxf(acc.w, v.w);
    }
    *reinterpret_cast<float4*>(&agg[(size_t)node * DD + lane * 4]) = acc;
}

// ---------------------------------------------------------------------------
// mma / ldmatrix / cp.async helpers
// ---------------------------------------------------------------------------
__device__ __forceinline__ void mma16(float* c, const uint32_t* a,
                                      uint32_t b0, uint32_t b1)
{
    asm("mma.sync.aligned.m16n8k16.row.col.f32.bf16.bf16.f32 "
        "{%0,%1,%2,%3}, {%4,%5,%6,%7}, {%8,%9}, {%0,%1,%2,%3};\n"
        : "+f"(c[0]), "+f"(c[1]), "+f"(c[2]), "+f"(c[3])
        : "r"(a[0]), "r"(a[1]), "r"(a[2]), "r"(a[3]),
          "r"(b0), "r"(b1));
}

__device__ __forceinline__ void ldmx4(uint32_t* r, uint32_t addr)
{
    asm volatile(
        "ldmatrix.sync.aligned.m8n8.x4.shared.b16 {%0,%1,%2,%3}, [%4];"
        : "=r"(r[0]), "=r"(r[1]), "=r"(r[2]), "=r"(r[3]) : "r"(addr));
}

__device__ __forceinline__ void cp16(uint32_t saddr, const void* gaddr)
{
    asm volatile("cp.async.cg.shared.global [%0], [%1], 16;\n"
                 :: "r"(saddr), "l"(gaddr));
}
__device__ __forceinline__ void cp_commit()
{ asm volatile("cp.async.commit_group;\n"); }
__device__ __forceinline__ void cp_wait0()
{ asm volatile("cp.async.wait_group 0;\n"); }

__device__ __forceinline__ uint32_t pack_bf16x2(float a, float b)
{
    __nv_bfloat162 h = __floats2bfloat162_rn(a, b);
    return *reinterpret_cast<uint32_t*>(&h);
}

// ---------------------------------------------------------------------------
// Dual-source bf16-split tensor-core GEMM, BN=64 column tiles.
// A AND B double-buffered -> single __syncthreads per k-tile.
//   C[:, coff:coff+64] = relu(A1 @ W1 [+ A2 @ W2] + bias), K = 128.
// ---------------------------------------------------------------------------
template<bool FUSE_LSM>
__global__ void __launch_bounds__(256, 2)
sage_gemm_bf16(const float* __restrict__ A1,
               const __nv_bfloat16* __restrict__ B1h,
               const __nv_bfloat16* __restrict__ B1l,
               const float* __restrict__ A2,
               const __nv_bfloat16* __restrict__ B2h,
               const __nv_bfloat16* __restrict__ B2l,
               const float* __restrict__ bias, float* __restrict__ C,
               int N, int M)
{
    constexpr int BM   = 128;
    constexpr int BN   = 64;
    constexpr int BK   = 64;
    constexpr int STRP = 36;          // u32 per row (32 data + 4 pad)
    constexpr int NT   = 4;
    constexpr int NP   = 2;
    constexpr int ABUF = BM * STRP;   // u32 per A plane
    constexpr int BBUF = BN * STRP;   // u32 per B plane

    // layout: Abuf0[hi|lo] Abuf1[hi|lo] Bbuf0[hi|lo] Bbuf1[hi|lo]
    extern __shared__ __align__(16) uint32_t smem_u[];
    uint32_t* Asmem = smem_u;                 // 2 bufs x 2 planes x ABUF
    uint32_t* Bsmem = smem_u + 4 * ABUF;      // 2 bufs x 2 planes x BBUF

    const int tid  = threadIdx.x;
    const int lane = tid & 31;
    const int warp = tid >> 5;
    const int wm   = warp & 3;
    const int wn   = warp >> 2;
    const int t4   = lane & 3;
    const int brow = blockIdx.y * BM;
    const int coff = blockIdx.x * BN;

    B1h += (size_t)coff * DD;
    B1l += (size_t)coff * DD;
    if (B2h) { B2h += (size_t)coff * DD; B2l += (size_t)coff * DD; }
    bias += coff;

    const uint32_t as_b = (uint32_t)__cvta_generic_to_shared(Asmem);
    const uint32_t bs_b = (uint32_t)__cvta_generic_to_shared(Bsmem);

    const uint32_t a_row_off = (uint32_t)(lane & 15) * STRP + (uint32_t)(lane >> 4) * 4;
    const uint32_t b_row_off = ((uint32_t)(lane & 7) + (uint32_t)(lane >> 4) * 8) * STRP
                             + (uint32_t)((lane >> 3) & 1) * 4;

    const float* Ab[2]          = { A1, A2 ? A2 : A1 };
    const __nv_bfloat16* Bhb[2] = { B1h, B2h ? B2h : B1h };
    const __nv_bfloat16* Blb[2] = { B1l, B2l ? B2l : B1l };
    const int T = A2 ? 4 : 2;

    float c[2][NT][4];
    #pragma unroll
    for (int mt = 0; mt < 2; mt++)
        #pragma unroll
        for (int nt = 0; nt < NT; nt++)
            #pragma unroll
            for (int i = 0; i < 4; i++) c[mt][nt][i] = 0.0f;

    float4 areg[8];

    #define LOAD_A_REG(t_) do {                                               \
        const float* A_ = Ab[(t_) >> 1];                                      \
        int koff_ = ((t_) & 1) * BK;                                          \
        _Pragma("unroll")                                                     \
        for (int l = 0; l < 8; l++) {                                         \
            int idx = tid + l * 256;                                          \
            int r   = idx >> 4;                                               \
            int c4  = idx & 15;                                               \
            int grow = brow + r;                                              \
            areg[l] = (grow < N)                                              \
                ? *reinterpret_cast<const float4*>(                           \
                      &A_[(size_t)grow * DD + koff_ + c4 * 4])                \
                : make_float4(0.f, 0.f, 0.f, 0.f);                            \
        }                                                                     \
    } while (0)

    #define STORE_A_SMEM(buf_) do {                                           \
        uint32_t* Ah_ = Asmem + (buf_) * 2 * ABUF;                            \
        uint32_t* Al_ = Ah_ + ABUF;                                           \
        _Pragma("unroll")                                                     \
        for (int l = 0; l < 8; l++) {                                         \
            int idx = tid + l * 256;                                          \
            int r   = idx >> 4;                                               \
            int c4  = idx & 15;                                               \
            float4 v = areg[l];                                               \
            float hx = __bfloat162float(__float2bfloat16(v.x));               \
            float hy = __bfloat162float(__float2bfloat16(v.y));               \
            float hz = __bfloat162float(__float2bfloat16(v.z));               \
            float hw = __bfloat162float(__float2bfloat16(v.w));               \
            uint32_t* ph = &Ah_[r * STRP + c4 * 2];                           \
            uint32_t* pl = &Al_[r * STRP + c4 * 2];                           \
            ph[0] = pack_bf16x2(hx, hy);                                      \
            ph[1] = pack_bf16x2(hz, hw);                                      \
            pl[0] = pack_bf16x2(v.x - hx, v.y - hy);                          \
            pl[1] = pack_bf16x2(v.z - hz, v.w - hw);                          \
        }                                                                     \
    } while (0)

    #define CPASYNC_B(t_, buf_) do {                                          \
        const __nv_bfloat16* Bh_ = Bhb[(t_) >> 1] + ((t_) & 1) * BK;          \
        const __nv_bfloat16* Bl_ = Blb[(t_) >> 1] + ((t_) & 1) * BK;          \
        uint32_t hi_base = bs_b + (uint32_t)(buf_) * 2u * BBUF * 4u;          \
        uint32_t lo_base = hi_base + (uint32_t)BBUF * 4u;                     \
        _Pragma("unroll")                                                     \
        for (int l = 0; l < 2; l++) {                                         \
            int idx = tid + l * 256;                                          \
            int n   = idx >> 3;                                               \
            int q   = idx & 7;                                                \
            uint32_t so = (uint32_t)(n * STRP + q * 4) * 4u;                  \
            cp16(hi_base + so, &Bh_[(size_t)n * DD + q * 8]);                 \
            cp16(lo_base + so, &Bl_[(size_t)n * DD + q * 8]);                 \
        }                                                                     \
        cp_commit();                                                          \
    } while (0)

    // ---- prologue: tile 0 into buffer 0 ----
    LOAD_A_REG(0);
    CPASYNC_B(0, 0);
    STORE_A_SMEM(0);
    cp_wait0();
    __syncthreads();

    // ---- pipelined main loop: ONE barrier per k-tile ----
    #pragma unroll 1
    for (int t = 0; t < T; t++) {
        int buf = t & 1;
        bool has_next = (t + 1 < T);
        if (has_next) {
            LOAD_A_REG(t + 1);          // gmem latency hidden under MMAs
            CPASYNC_B(t + 1, buf ^ 1);
        }

        uint32_t ahi_base = as_b + (uint32_t)buf * 2u * ABUF * 4u;
        uint32_t alo_base = ahi_base + (uint32_t)ABUF * 4u;
        uint32_t bhi_base = bs_b + (uint32_t)buf * 2u * BBUF * 4u;
        uint32_t blo_base = bhi_base + (uint32_t)BBUF * 4u;

        #pragma unroll
        for (int ks = 0; ks < BK / 16; ks++) {
            int kp = ks * 8;
            uint32_t ah[2][4], al[2][4], bh[NP][4], bl[NP][4];
            #pragma unroll
            for (int mt = 0; mt < 2; mt++) {
                uint32_t off = ((uint32_t)(wm * 32 + mt * 16) * STRP
                                + (uint32_t)kp + a_row_off) * 4u;
                ldmx4(ah[mt], ahi_base + off);
                ldmx4(al[mt], alo_base + off);
            }
            #pragma unroll
            for (int p = 0; p < NP; p++) {
                uint32_t off = ((uint32_t)(wn * 32 + p * 16) * STRP
                                + (uint32_t)kp + b_row_off) * 4u;
                ldmx4(bh[p], bhi_base + off);
                ldmx4(bl[p], blo_base + off);
            }
            #pragma unroll
            for (int p = 0; p < NP; p++)
                #pragma unroll
                for (int sub = 0; sub < 2; sub++)
                    #pragma unroll
                    for (int mt = 0; mt < 2; mt++)
                        mma16(c[mt][p*2+sub], ah[mt], bh[p][2*sub], bh[p][2*sub+1]);
            #pragma unroll
            for (int p = 0; p < NP; p++)
                #pragma unroll
                for (int sub = 0; sub < 2; sub++)
                    #pragma unroll
                    for (int mt = 0; mt < 2; mt++)
                        mma16(c[mt][p*2+sub], ah[mt], bl[p][2*sub], bl[p][2*sub+1]);
            #pragma unroll
            for (int p = 0; p < NP; p++)
                #pragma unroll
                for (int sub = 0; sub < 2; sub++)
                    #pragma unroll
                    for (int mt = 0; mt < 2; mt++)
                        mma16(c[mt][p*2+sub], al[mt], bh[p][2*sub], bh[p][2*sub+1]);
        }

        if (has_next) {
            STORE_A_SMEM(buf ^ 1);      // other buffer: no race with readers
            cp_wait0();                 // next B landed
        }
        __syncthreads();                // single barrier: orders everything
    }

    const int g = lane >> 2;

    if (!FUSE_LSM) {
        #pragma unroll
        for (int mt = 0; mt < 2; mt++) {
            int row = brow + wm * 32 + mt * 16 + g;
            #pragma unroll
            for (int nt = 0; nt < NT; nt++) {
                int col = wn * 32 + nt * 8 + 2 * t4;
                float b0 = bias[col], b1 = bias[col + 1];
                int gcol = coff + col;
                if (row < N) {
                    float2 v;
                    v.x = fmaxf(c[mt][nt][0] + b0, 0.0f);
                    v.y = fmaxf(c[mt][nt][1] + b1, 0.0f);
                    *reinterpret_cast<float2*>(&C[(size_t)row * M + gcol]) = v;
                }
                if (row + 8 < N) {
                    float2 v;
                    v.x = fmaxf(c[mt][nt][2] + b0, 0.0f);
                    v.y = fmaxf(c[mt][nt][3] + b1, 0.0f);
                    *reinterpret_cast<float2*>(&C[(size_t)(row + 8) * M + gcol]) = v;
                }
            }
        }
    } else {
        constexpr int SSTR = 68;
        float* sf = reinterpret_cast<float*>(smem_u);   // 128 x 68 x 4 = 34816 B
        #pragma unroll
        for (int mt = 0; mt < 2; mt++) {
            int rl = wm * 32 + mt * 16 + g;
            #pragma unroll
            for (int nt = 0; nt < NT; nt++) {
                int col = wn * 32 + nt * 8 + 2 * t4;
                float b0 = bias[col], b1 = bias[col + 1];
                float2 v0, v1;
                v0.x = fmaxf(c[mt][nt][0] + b0, 0.0f);
                v0.y = fmaxf(c[mt][nt][1] + b1, 0.0f);
                v1.x = fmaxf(c[mt][nt][2] + b0, 0.0f);
                v1.y = fmaxf(c[mt][nt][3] + b1, 0.0f);
                *reinterpret_cast<float2*>(&sf[rl * SSTR + col])       = v0;
                *reinterpret_cast<float2*>(&sf[(rl + 8) * SSTR + col]) = v1;
            }
        }
        __syncthreads();
        #pragma unroll 1
        for (int r = warp; r < BM; r += 8) {
            int grow = brow + r;
            if (grow >= N) continue;
            float v0 = sf[r * SSTR + lane];
            float v1 = sf[r * SSTR + lane + 32];
            float mx = fmaxf(v0, v1);
            #pragma unroll
            for (int o = 16; o; o >>= 1)
                mx = fmaxf(mx, __shfl_xor_sync(0xFFFFFFFFu, mx, o));
            float s = expf(v0 - mx) + expf(v1 - mx);
            #pragma unroll
            for (int o = 16; o; o >>= 1)
                s += __shfl_xor_sync(0xFFFFFFFFu, s, o);
            float lse = logf(s) + mx;
            C[(size_t)grow * NCLS + lane]      = v0 - lse;
            C[(size_t)grow * NCLS + lane + 32] = v1 - lse;
        }
    }
    #undef LOAD_A_REG
    #undef STORE_A_SMEM
    #undef CPASYNC_B
}

// ---------------------------------------------------------------------------
// Launch
// ---------------------------------------------------------------------------
extern "C" void kernel_launch(void* const* d_in, const int* in_sizes, int n_in,
                              void* d_out, int out_size)
{
    const float* x    = (const float*)d_in[0];
    const int*   esrc = (const int*)  d_in[1];
    const int*   edst = (const int*)  d_in[2];

    const float* Wp[3], *bp[3], *Ws[3], *Wn[3], *bn[3];
    for (int i = 0; i < 3; i++) {
        Wp[i] = (const float*)d_in[3 + 5 * i + 0];
        bp[i] = (const float*)d_in[3 + 5 * i + 1];
        Ws[i] = (const float*)d_in[3 + 5 * i + 2];
        Wn[i] = (const float*)d_in[3 + 5 * i + 3];
        bn[i] = (const float*)d_in[3 + 5 * i + 4];
    }

    float *m_p, *agg_p, *h1_p, *h2_p;
    cudaGetSymbolAddress((void**)&m_p,   g_m);
    cudaGetSymbolAddress((void**)&agg_p, g_agg);
    cudaGetSymbolAddress((void**)&h1_p,  g_h1);
    cudaGetSymbolAddress((void**)&h2_p,  g_h2);
    __nv_bfloat16 *wh_p, *wl_p;
    cudaGetSymbolAddress((void**)&wh_p, g_wh);
    cudaGetSymbolAddress((void**)&wl_p, g_wl);

    const int N = NN, E = EE;

    // smem: A 2 bufs x 2 planes x 128*36 + B 2 bufs x 2 planes x 64*36 (u32)
    size_t smemG = (size_t)(4 * 128 * 36 + 4 * 64 * 36) * 4;   // 110592
    cudaFuncSetAttribute(sage_gemm_bf16<false>,
                         cudaFuncAttributeMaxDynamicSharedMemorySize, (int)smemG);
    cudaFuncSetAttribute(sage_gemm_bf16<true>,
                         cudaFuncAttributeMaxDynamicSharedMemorySize, (int)smemG);

    // launch 1: weight prep
    WPrep wp;
    const float* wsrc[9] = { Wp[0], Ws[0], Wn[0],
                             Wp[1], Ws[1], Wn[1],
                             Wp[2], Ws[2], Wn[2] };
    int wM[9] = { DD, DD, DD, DD, DD, DD, DD, NCLS, NCLS };
    for (int i = 0; i < 9; i++) { wp.src[i] = wsrc[i]; wp.M[i] = wM[i]; }
    prep_weights<<<dim3((DD * DD + 255) / 256, 9), 256>>>(wp, wh_p, wl_p);

    // launch 2: zero degrees
    zero_deg_kernel<<<(NN + 255) / 256, 256>>>();

    // launch 3: edge count
    count_kernel<<<(E + 255) / 256, 256>>>(edst);

    const int RT = (N + 127) / 128;           // 782 row tiles
    dim3 grid2(2, RT);
    dim3 grid1(1, RT);

    // launch 4: layer-0 pool GEMM (profiled slot)
    sage_gemm_bf16<false><<<grid2, 256, smemG>>>(
        x, wh_p + 0 * DD * DD, wl_p + 0 * DD * DD,
        nullptr, nullptr, nullptr, bp[0], m_p, N, DD);

    // launches 5-7: CSR build part 2 (independent of GEMM)
    const int SCAN_BLKS = (NN + 1023) / 1024;    // 98
    scan1_kernel<<<SCAN_BLKS, 256>>>();
    scan3_kernel<<<SCAN_BLKS, 256>>>(SCAN_BLKS);
    fill_kernel<<<(E + 255) / 256, 256>>>(esrc, edst);

    const float* h = x;
    float* hbuf[2] = { h1_p, h2_p };

    for (int layer = 0; layer < 3; layer++) {
        const __nv_bfloat16* wph = wh_p + (layer * 3 + 0) * DD * DD;
        const __nv_bfloat16* wpl = wl_p + (layer * 3 + 0) * DD * DD;
        const __nv_bfloat16* wsh = wh_p + (layer * 3 + 1) * DD * DD;
        const __nv_bfloat16* wsl = wl_p + (layer * 3 + 1) * DD * DD;
        const __nv_bfloat16* wnh = wh_p + (layer * 3 + 2) * DD * DD;
        const __nv_bfloat16* wnl = wl_p + (layer * 3 + 2) * DD * DD;

        // 1) m = relu(h @ Wp + bp)  (layer 0 issued above)
        if (layer > 0) {
            sage_gemm_bf16<false><<<grid2, 256, smemG>>>(
                h, wph, wpl, nullptr, nullptr, nullptr,
                bp[layer], m_p, N, DD);
        }

        // 2) agg = segment_max(m[src], dst) via CSR gather-max
        aggregate_kernel<<<(N + 7) / 8, 256>>>(m_p, agg_p, N);

        // 3) h' = relu(h @ Ws + agg @ Wn + bn)  (final layer fuses log-softmax)
        if (layer < 2) {
            float* out = hbuf[layer & 1];
            sage_gemm_bf16<false><<<grid2, 256, smemG>>>(
                h, wsh, wsl, agg_p, wnh, wnl, bn[layer], out, N, DD);
            h = out;
        } else {
            sage_gemm_bf16<true><<<grid1, 256, smemG>>>(
                h, wsh, wsl, agg_p, wnh, wnl, bn[layer],
                (float*)d_out, N, NCLS);
        }
    }
}

// round 16
// speedup vs baseline: 1.5802x; 1.1153x over previous
#include <cuda_runtime.h>
#include <cuda_bf16.h>
#include <cstdint>
#include <cstddef>

#define NN 100000
#define EE 800000
#define DD 128
#define NCLS 64

// ---------------------------------------------------------------------------
// Scratch (no runtime allocation allowed)
// ---------------------------------------------------------------------------
__device__ float g_m  [(size_t)NN * DD];
__device__ float g_agg[(size_t)NN * DD];
__device__ float g_h1 [(size_t)NN * DD];
__device__ float g_h2 [(size_t)NN * DD];
__device__ __nv_bfloat16 g_wh[9][DD * DD];
__device__ __nv_bfloat16 g_wl[9][DD * DD];
__device__ int g_deg[NN];
__device__ int g_off[NN];
__device__ int g_cur[NN];
__device__ int g_csr[EE];
__device__ int g_part[128];

// ---------------------------------------------------------------------------
// Weight prep
// ---------------------------------------------------------------------------
struct WPrep { const float* src[9]; int M[9]; };

__global__ void prep_weights(WPrep p, __nv_bfloat16* __restrict__ hi,
                             __nv_bfloat16* __restrict__ lo)
{
    int w = blockIdx.y;
    int M = p.M[w];
    int idx = blockIdx.x * blockDim.x + threadIdx.x;
    if (idx >= DD * M) return;
    int k = idx / M;
    int m = idx % M;
    float v = p.src[w][idx];
    __nv_bfloat16 h = __float2bfloat16(v);
    float r = v - __bfloat162float(h);
    hi[(size_t)w * DD * DD + m * DD + k] = h;
    lo[(size_t)w * DD * DD + m * DD + k] = __float2bfloat16(r);
}

// ---------------------------------------------------------------------------
// CSR build (scan2 folded into scan3)
// ---------------------------------------------------------------------------
__global__ void zero_deg_kernel()
{
    int i = blockIdx.x * blockDim.x + threadIdx.x;
    if (i < NN) g_deg[i] = 0;
}

__global__ void count_kernel(const int* __restrict__ dst)
{
    int e = blockIdx.x * blockDim.x + threadIdx.x;
    if (e < EE) atomicAdd(&g_deg[dst[e]], 1);
}

__global__ void scan1_kernel()
{
    __shared__ int sh[256];
    int tid = threadIdx.x;
    int base = blockIdx.x * 1024 + tid * 4;
    int s = 0;
    #pragma unroll
    for (int j = 0; j < 4; j++) {
        int idx = base + j;
        if (idx < NN) s += g_deg[idx];
    }
    sh[tid] = s;
    __syncthreads();
    for (int o = 128; o; o >>= 1) {
        if (tid < o) sh[tid] += sh[tid + o];
        __syncthreads();
    }
    if (tid == 0) g_part[blockIdx.x] = sh[0];
}

__global__ void scan3_kernel(int nblk)
{
    __shared__ int sh[256];
    int tid = threadIdx.x;
    int base = blockIdx.x * 1024 + tid * 4;
    int v[4];
    int s = 0;
    #pragma unroll
    for (int j = 0; j < 4; j++) {
        int idx = base + j;
        v[j] = (idx < NN) ? g_deg[idx] : 0;
        s += v[j];
    }
    sh[tid] = s;
    __syncthreads();
    #pragma unroll
    for (int o = 1; o < 256; o <<= 1) {
        int x = (tid >= o) ? sh[tid - o] : 0;
        __syncthreads();
        sh[tid] += x;
        __syncthreads();
    }
    // block prefix: sum of earlier blocks' totals (raw totals from scan1)
    int pre = 0;
    for (int i = 0; i < blockIdx.x; i++) pre += __ldg(&g_part[i]);
    int run = sh[tid] - s + pre;
    #pragma unroll
    for (int j = 0; j < 4; j++) {
        int idx = base + j;
        if (idx < NN) { g_off[idx] = run; g_cur[idx] = run; }
        run += v[j];
    }
}

__global__ void fill_kernel(const int* __restrict__ src,
                            const int* __restrict__ dst)
{
    int e = blockIdx.x * blockDim.x + threadIdx.x;
    if (e < EE) {
        int p = atomicAdd(&g_cur[dst[e]], 1);
        g_csr[p] = src[e];
    }
}

// ---------------------------------------------------------------------------
// Aggregation: warp per node, gather-max (no atomics), unrolled x4
// ---------------------------------------------------------------------------
__global__ void aggregate_kernel(const float* __restrict__ m,
                                 float* __restrict__ agg, int N)
{
    int node = blockIdx.x * 8 + (threadIdx.x >> 5);
    int lane = threadIdx.x & 31;
    if (node >= N) return;
    int o = g_off[node];
    int d = g_deg[node];
    float4 acc = make_float4(0.f, 0.f, 0.f, 0.f);
    int i = 0;
    for (; i + 4 <= d; i += 4) {
        int s0 = g_csr[o + i + 0];
        int s1 = g_csr[o + i + 1];
        int s2 = g_csr[o + i + 2];
        int s3 = g_csr[o + i + 3];
        float4 v0 = *reinterpret_cast<const float4*>(&m[(size_t)s0 * DD + lane * 4]);
        float4 v1 = *reinterpret_cast<const float4*>(&m[(size_t)s1 * DD + lane * 4]);
        float4 v2 = *reinterpret_cast<const float4*>(&m[(size_t)s2 * DD + lane * 4]);
        float4 v3 = *reinterpret_cast<const float4*>(&m[(size_t)s3 * DD + lane * 4]);
        acc.x = fmaxf(fmaxf(acc.x, fmaxf(v0.x, v1.x)), fmaxf(v2.x, v3.x));
        acc.y = fmaxf(fmaxf(acc.y, fmaxf(v0.y, v1.y)), fmaxf(v2.y, v3.y));
        acc.z = fmaxf(fmaxf(acc.z, fmaxf(v0.z, v1.z)), fmaxf(v2.z, v3.z));
        acc.w = fmaxf(fmaxf(acc.w, fmaxf(v0.w, v1.w)), fmaxf(v2.w, v3.w));
    }
    for (; i < d; i++) {
        int s = g_csr[o + i];
        float4 v = *reinterpret_cast<const float4*>(&m[(size_t)s * DD + lane * 4]);
        acc.x = fmaxf(acc.x, v.x);
        acc.y = fmaxf(acc.y, v.y);
        acc.z = fmaxf(acc.z, v.z);
        acc.w = fmaxf(acc.w, v.w);
    }
    *reinterpret_cast<float4*>(&agg[(size_t)node * DD + lane * 4]) = acc;
}

// ---------------------------------------------------------------------------
// mma / ldmatrix / cp.async helpers
// NOTE: mma16 is intentionally NOT volatile — pure register op, lets ptxas
// interleave independent accumulator chains.
// ---------------------------------------------------------------------------
__device__ __forceinline__ void mma16(float* c, const uint32_t* a,
                                      uint32_t b0, uint32_t b1)
{
    asm("mma.sync.aligned.m16n8k16.row.col.f32.bf16.bf16.f32 "
        "{%0,%1,%2,%3}, {%4,%5,%6,%7}, {%8,%9}, {%0,%1,%2,%3};\n"
        : "+f"(c[0]), "+f"(c[1]), "+f"(c[2]), "+f"(c[3])
        : "r"(a[0]), "r"(a[1]), "r"(a[2]), "r"(a[3]),
          "r"(b0), "r"(b1));
}

__device__ __forceinline__ void ldmx4(uint32_t* r, uint32_t addr)
{
    asm volatile(
        "ldmatrix.sync.aligned.m8n8.x4.shared.b16 {%0,%1,%2,%3}, [%4];"
        : "=r"(r[0]), "=r"(r[1]), "=r"(r[2]), "=r"(r[3]) : "r"(addr));
}

__device__ __forceinline__ void cp16(uint32_t saddr, const void* gaddr)
{
    asm volatile("cp.async.cg.shared.global [%0], [%1], 16;\n"
                 :: "r"(saddr), "l"(gaddr));
}
__device__ __forceinline__ void cp_commit()
{ asm volatile("cp.async.commit_group;\n"); }
__device__ __forceinline__ void cp_wait0()
{ asm volatile("cp.async.wait_group 0;\n"); }

__device__ __forceinline__ uint32_t pack_bf16x2(float a, float b)
{
    __nv_bfloat162 h = __floats2bfloat162_rn(a, b);
    return *reinterpret_cast<uint32_t*>(&h);
}

// ---------------------------------------------------------------------------
// Dual-source bf16-split tensor-core GEMM, BN=64 column tiles.
//   C[:, coff:coff+64] = relu(A1 @ W1 [+ A2 @ W2] + bias), K = 128.
// grid = (n_col_tiles, n_row_tiles). Per k-step: one 8-wide ldmatrix burst
// (4 A + 4 B fragments, independent) then 24 MMAs product-major.
// ---------------------------------------------------------------------------
template<bool FUSE_LSM>
__global__ void __launch_bounds__(256, 2)
sage_gemm_bf16(const float* __restrict__ A1,
               const __nv_bfloat16* __restrict__ B1h,
               const __nv_bfloat16* __restrict__ B1l,
               const float* __restrict__ A2,
               const __nv_bfloat16* __restrict__ B2h,
               const __nv_bfloat16* __restrict__ B2l,
               const float* __restrict__ bias, float* __restrict__ C,
               int N, int M)
{
    constexpr int BM   = 128;
    constexpr int BN   = 64;
    constexpr int BK   = 64;
    constexpr int STRP = 36;          // u32 per row (32 data + 4 pad)
    constexpr int NT   = 4;           // n8 tiles per warp (32 cols / 8)
    constexpr int NP   = 2;           // n16 ldmatrix groups per warp
    constexpr int BBUF = BN * STRP;

    extern __shared__ __align__(16) uint32_t smem_u[];
    uint32_t* As_hi = smem_u;
    uint32_t* As_lo = As_hi + BM * STRP;
    uint32_t* Bs    = As_lo + BM * STRP;

    const int tid  = threadIdx.x;
    const int lane = tid & 31;
    const int warp = tid >> 5;
    const int wm   = warp & 3;
    const int wn   = warp >> 2;
    const int t4   = lane & 3;
    const int brow = blockIdx.y * BM;
    const int coff = blockIdx.x * BN;     // column tile offset

    // offset weight planes / bias to this column tile
    B1h += (size_t)coff * DD;
    B1l += (size_t)coff * DD;
    if (B2h) { B2h += (size_t)coff * DD; B2l += (size_t)coff * DD; }
    bias += coff;

    const uint32_t as_hi_b = (uint32_t)__cvta_generic_to_shared(As_hi);
    const uint32_t as_lo_b = (uint32_t)__cvta_generic_to_shared(As_lo);
    const uint32_t bs_b    = (uint32_t)__cvta_generic_to_shared(Bs);

    const uint32_t a_row_off = (uint32_t)(lane & 15) * STRP + (uint32_t)(lane >> 4) * 4;
    const uint32_t b_row_off = ((uint32_t)(lane & 7) + (uint32_t)(lane >> 4) * 8) * STRP
                             + (uint32_t)((lane >> 3) & 1) * 4;

    const float* Ab[2]          = { A1, A2 ? A2 : A1 };
    const __nv_bfloat16* Bhb[2] = { B1h, B2h ? B2h : B1h };
    const __nv_bfloat16* Blb[2] = { B1l, B2l ? B2l : B1l };
    const int T = A2 ? 4 : 2;

    float c[2][NT][4];
    #pragma unroll
    for (int mt = 0; mt < 2; mt++)
        #pragma unroll
        for (int nt = 0; nt < NT; nt++)
            #pragma unroll
            for (int i = 0; i < 4; i++) c[mt][nt][i] = 0.0f;

    float4 areg[8];

    #define LOAD_A_REG(t_) do {                                               \
        const float* A_ = Ab[(t_) >> 1];                                      \
        int koff_ = ((t_) & 1) * BK;                                          \
        _Pragma("unroll")                                                     \
        for (int l = 0; l < 8; l++) {                                         \
            int idx = tid + l * 256;                                          \
            int r   = idx >> 4;                                               \
            int c4  = idx & 15;                                               \
            int grow = brow + r;                                              \
            areg[l] = (grow < N)                                              \
                ? *reinterpret_cast<const float4*>(                           \
                      &A_[(size_t)grow * DD + koff_ + c4 * 4])                \
                : make_float4(0.f, 0.f, 0.f, 0.f);                            \
        }                                                                     \
    } while (0)

    #define STORE_A_SMEM() do {                                               \
        _Pragma("unroll")                                                     \
        for (int l = 0; l < 8; l++) {                                         \
            int idx = tid + l * 256;                                          \
            int r   = idx >> 4;                                               \
            int c4  = idx & 15;                                               \
            float4 v = areg[l];                                               \
            float hx = __bfloat162float(__float2bfloat16(v.x));               \
            float hy = __bfloat162float(__float2bfloat16(v.y));               \
            float hz = __bfloat162float(__float2bfloat16(v.z));               \
            float hw = __bfloat162float(__float2bfloat16(v.w));               \
            uint32_t* ph = &As_hi[r * STRP + c4 * 2];                         \
            uint32_t* pl = &As_lo[r * STRP + c4 * 2];                         \
            ph[0] = pack_bf16x2(hx, hy);                                      \
            ph[1] = pack_bf16x2(hz, hw);                                      \
            pl[0] = pack_bf16x2(v.x - hx, v.y - hy);                          \
            pl[1] = pack_bf16x2(v.z - hz, v.w - hw);                          \
        }                                                                     \
    } while (0)

    // BN*8/256 = 2 iterations
    #define CPASYNC_B(t_, buf_) do {                                          \
        const __nv_bfloat16* Bh_ = Bhb[(t_) >> 1] + ((t_) & 1) * BK;          \
        const __nv_bfloat16* Bl_ = Blb[(t_) >> 1] + ((t_) & 1) * BK;          \
        uint32_t hi_base = bs_b + (uint32_t)(buf_) * 2u * BBUF * 4u;          \
        uint32_t lo_base = hi_base + (uint32_t)BBUF * 4u;                     \
        _Pragma("unroll")                                                     \
        for (int l = 0; l < 2; l++) {                                         \
            int idx = tid + l * 256;                                          \
            int n   = idx >> 3;                                               \
            int q   = idx & 7;                                                \
            uint32_t so = (uint32_t)(n * STRP + q * 4) * 4u;                  \
            cp16(hi_base + so, &Bh_[(size_t)n * DD + q * 8]);                 \
            cp16(lo_base + so, &Bl_[(size_t)n * DD + q * 8]);                 \
        }                                                                     \
        cp_commit();                                                          \
    } while (0)

    // ---- prologue: tile 0 ----
    LOAD_A_REG(0);
    CPASYNC_B(0, 0);
    STORE_A_SMEM();
    cp_wait0();
    __syncthreads();

    // ---- pipelined main loop over k-tiles ----
    #pragma unroll 1
    for (int t = 0; t < T; t++) {
        int buf = t & 1;
        bool has_next = (t + 1 < T);
        if (has_next) {
            LOAD_A_REG(t + 1);          // gmem latency hidden under MMAs
            CPASYNC_B(t + 1, buf ^ 1);
        }

        uint32_t bhi_base = bs_b + (uint32_t)buf * 2u * BBUF * 4u;
        uint32_t blo_base = bhi_base + (uint32_t)BBUF * 4u;

        #pragma unroll
        for (int ks = 0; ks < BK / 16; ks++) {
            int kp = ks * 8;
            uint32_t ah[2][4], al[2][4], bh[NP][4], bl[NP][4];
            // ---- single 8-wide independent ldmatrix burst ----
            #pragma unroll
            for (int mt = 0; mt < 2; mt++) {
                uint32_t off = ((uint32_t)(wm * 32 + mt * 16) * STRP
                                + (uint32_t)kp + a_row_off) * 4u;
                ldmx4(ah[mt], as_hi_b + off);
                ldmx4(al[mt], as_lo_b + off);
            }
            #pragma unroll
            for (int p = 0; p < NP; p++) {
                uint32_t off = ((uint32_t)(wn * 32 + p * 16) * STRP
                                + (uint32_t)kp + b_row_off) * 4u;
                ldmx4(bh[p], bhi_base + off);
                ldmx4(bl[p], blo_base + off);
            }
            // ---- 24 MMAs, product-major (dependent distance 8) ----
            #pragma unroll
            for (int p = 0; p < NP; p++)
                #pragma unroll
                for (int sub = 0; sub < 2; sub++)
                    #pragma unroll
                    for (int mt = 0; mt < 2; mt++)
                        mma16(c[mt][p*2+sub], ah[mt], bh[p][2*sub], bh[p][2*sub+1]);
            #pragma unroll
            for (int p = 0; p < NP; p++)
                #pragma unroll
                for (int sub = 0; sub < 2; sub++)
                    #pragma unroll
                    for (int mt = 0; mt < 2; mt++)
                        mma16(c[mt][p*2+sub], ah[mt], bl[p][2*sub], bl[p][2*sub+1]);
            #pragma unroll
            for (int p = 0; p < NP; p++)
                #pragma unroll
                for (int sub = 0; sub < 2; sub++)
                    #pragma unroll
                    for (int mt = 0; mt < 2; mt++)
                        mma16(c[mt][p*2+sub], al[mt], bh[p][2*sub], bh[p][2*sub+1]);
        }
        __syncthreads();                // done reading As + Bs[buf]
        if (has_next) {
            STORE_A_SMEM();             // write next A tile
            cp_wait0();                 // next B landed
            __syncthreads();
        }
    }

    const int g = lane >> 2;

    if (!FUSE_LSM) {
        // ---- epilogue: bias + relu -> gmem ----
        #pragma unroll
        for (int mt = 0; mt < 2; mt++) {
            int row = brow + wm * 32 + mt * 16 + g;
            #pragma unroll
            for (int nt = 0; nt < NT; nt++) {
                int col = wn * 32 + nt * 8 + 2 * t4;    // local col in tile
                float b0 = bias[col], b1 = bias[col + 1];
                int gcol = coff + col;
                if (row < N) {
                    float2 v;
                    v.x = fmaxf(c[mt][nt][0] + b0, 0.0f);
                    v.y = fmaxf(c[mt][nt][1] + b1, 0.0f);
                    *reinterpret_cast<float2*>(&C[(size_t)row * M + gcol]) = v;
                }
                if (row + 8 < N) {
                    float2 v;
                    v.x = fmaxf(c[mt][nt][2] + b0, 0.0f);
                    v.y = fmaxf(c[mt][nt][3] + b1, 0.0f);
                    *reinterpret_cast<float2*>(&C[(size_t)(row + 8) * M + gcol]) = v;
                }
            }
        }
    } else {
        // ---- epilogue: bias + relu -> smem, then row log-softmax -> gmem ----
        constexpr int SSTR = 68;
        float* sf = reinterpret_cast<float*>(smem_u);   // 128 x 68 = 34816 B
        #pragma unroll
        for (int mt = 0; mt < 2; mt++) {
            int rl = wm * 32 + mt * 16 + g;
            #pragma unroll
            for (int nt = 0; nt < NT; nt++) {
                int col = wn * 32 + nt * 8 + 2 * t4;
                float b0 = bias[col], b1 = bias[col + 1];
                float2 v0, v1;
                v0.x = fmaxf(c[mt][nt][0] + b0, 0.0f);
                v0.y = fmaxf(c[mt][nt][1] + b1, 0.0f);
                v1.x = fmaxf(c[mt][nt][2] + b0, 0.0f);
                v1.y = fmaxf(c[mt][nt][3] + b1, 0.0f);
                *reinterpret_cast<float2*>(&sf[rl * SSTR + col])       = v0;
                *reinterpret_cast<float2*>(&sf[(rl + 8) * SSTR + col]) = v1;
            }
        }
        __syncthreads();
        #pragma unroll 1
        for (int r = warp; r < BM; r += 8) {
            int grow = brow + r;
            if (grow >= N) continue;           // warp-uniform
            float v0 = sf[r * SSTR + lane];
            float v1 = sf[r * SSTR + lane + 32];
            float mx = fmaxf(v0, v1);
            #pragma unroll
            for (int o = 16; o; o >>= 1)
                mx = fmaxf(mx, __shfl_xor_sync(0xFFFFFFFFu, mx, o));
            float s = expf(v0 - mx) + expf(v1 - mx);
            #pragma unroll
            for (int o = 16; o; o >>= 1)
                s += __shfl_xor_sync(0xFFFFFFFFu, s, o);
            float lse = logf(s) + mx;
            C[(size_t)grow * NCLS + lane]      = v0 - lse;
            C[(size_t)grow * NCLS + lane + 32] = v1 - lse;
        }
    }
    #undef LOAD_A_REG
    #undef STORE_A_SMEM
    #undef CPASYNC_B
}

// ---------------------------------------------------------------------------
// Launch
// ---------------------------------------------------------------------------
extern "C" void kernel_launch(void* const* d_in, const int* in_sizes, int n_in,
                              void* d_out, int out_size)
{
    const float* x    = (const float*)d_in[0];
    const int*   esrc = (const int*)  d_in[1];
    const int*   edst = (const int*)  d_in[2];

    const float* Wp[3], *bp[3], *Ws[3], *Wn[3], *bn[3];
    for (int i = 0; i < 3; i++) {
        Wp[i] = (const float*)d_in[3 + 5 * i + 0];
        bp[i] = (const float*)d_in[3 + 5 * i + 1];
        Ws[i] = (const float*)d_in[3 + 5 * i + 2];
        Wn[i] = (const float*)d_in[3 + 5 * i + 3];
        bn[i] = (const float*)d_in[3 + 5 * i + 4];
    }

    float *m_p, *agg_p, *h1_p, *h2_p;
    cudaGetSymbolAddress((void**)&m_p,   g_m);
    cudaGetSymbolAddress((void**)&agg_p, g_agg);
    cudaGetSymbolAddress((void**)&h1_p,  g_h1);
    cudaGetSymbolAddress((void**)&h2_p,  g_h2);
    __nv_bfloat16 *wh_p, *wl_p;
    cudaGetSymbolAddress((void**)&wh_p, g_wh);
    cudaGetSymbolAddress((void**)&wl_p, g_wl);

    const int N = NN, E = EE;

    // smem: A 2*128*36 + B 4*64*36, u32 units = 73728 B
    size_t smemG = (size_t)(2 * 128 * 36 + 4 * 64 * 36) * 4;
    cudaFuncSetAttribute(sage_gemm_bf16<false>,
                         cudaFuncAttributeMaxDynamicSharedMemorySize, (int)smemG);
    cudaFuncSetAttribute(sage_gemm_bf16<true>,
                         cudaFuncAttributeMaxDynamicSharedMemorySize, (int)smemG);

    // launch 1: weight prep
    WPrep wp;
    const float* wsrc[9] = { Wp[0], Ws[0], Wn[0],
                             Wp[1], Ws[1], Wn[1],
                             Wp[2], Ws[2], Wn[2] };
    int wM[9] = { DD, DD, DD, DD, DD, DD, DD, NCLS, NCLS };
    for (int i = 0; i < 9; i++) { wp.src[i] = wsrc[i]; wp.M[i] = wM[i]; }
    prep_weights<<<dim3((DD * DD + 255) / 256, 9), 256>>>(wp, wh_p, wl_p);

    // launch 2: zero degrees
    zero_deg_kernel<<<(NN + 255) / 256, 256>>>();

    // launch 3: edge count
    count_kernel<<<(E + 255) / 256, 256>>>(edst);

    const int RT = (N + 127) / 128;           // 782 row tiles
    dim3 grid2(2, RT);                        // two 64-col tiles
    dim3 grid1(1, RT);

    // launch 4: layer-0 pool GEMM (profiled slot)
    sage_gemm_bf16<false><<<grid2, 256, smemG>>>(
        x, wh_p + 0 * DD * DD, wl_p + 0 * DD * DD,
        nullptr, nullptr, nullptr, bp[0], m_p, N, DD);

    // launches 5-7: CSR build part 2 (independent of GEMM)
    const int SCAN_BLKS = (NN + 1023) / 1024;    // 98
    scan1_kernel<<<SCAN_BLKS, 256>>>();
    scan3_kernel<<<SCAN_BLKS, 256>>>(SCAN_BLKS);
    fill_kernel<<<(E + 255) / 256, 256>>>(esrc, edst);

    const float* h = x;
    float* hbuf[2] = { h1_p, h2_p };

    for (int layer = 0; layer < 3; layer++) {
        const __nv_bfloat16* wph = wh_p + (layer * 3 + 0) * DD * DD;
        const __nv_bfloat16* wpl = wl_p + (layer * 3 + 0) * DD * DD;
        const __nv_bfloat16* wsh = wh_p + (layer * 3 + 1) * DD * DD;
        const __nv_bfloat16* wsl = wl_p + (layer * 3 + 1) * DD * DD;
        const __nv_bfloat16* wnh = wh_p + (layer * 3 + 2) * DD * DD;
        const __nv_bfloat16* wnl = wl_p + (layer * 3 + 2) * DD * DD;

        // 1) m = relu(h @ Wp + bp)  (layer 0 issued above)
        if (layer > 0) {
            sage_gemm_bf16<false><<<grid2, 256, smemG>>>(
                h, wph, wpl, nullptr, nullptr, nullptr,
                bp[layer], m_p, N, DD);
        }

        // 2) agg = segment_max(m[src], dst) via CSR gather-max
        aggregate_kernel<<<(N + 7) / 8, 256>>>(m_p, agg_p, N);

        // 3) h' = relu(h @ Ws + agg @ Wn + bn)  (final layer fuses log-softmax)
        if (layer < 2) {
            float* out = hbuf[layer & 1];
            sage_gemm_bf16<false><<<grid2, 256, smemG>>>(
                h, wsh, wsl, agg_p, wnh, wnl, bn[layer], out, N, DD);
            h = out;
        } else {
            sage_gemm_bf16<true><<<grid1, 256, smemG>>>(
                h, wsh, wsl, agg_p, wnh, wnl, bn[layer],
                (float*)d_out, N, NCLS);
        }
    }
}